// round 12
// baseline (speedup 1.0000x reference)
#include <cuda_runtime.h>
#include <cuda_bf16.h>
#include <cstdint>

// Problem shape (fixed by dataset)
#define BB 64
#define LL 256
#define TT 1600
#define TC 64                       // time-chunk (2 halo periods)
#define SROW 65                     // smem row stride (floats), conflict-free
#define NCH 25                      // TT / TC
#define NBUF 2                      // pipeline depth
#define BUF_FLOATS (LL * SROW)      // 16640
#define SMEM_BYTES (NBUF * BUF_FLOATS * 4)   // 133,120 B
#define LN2 0.69314718055994531f
#define E_SENT (-(1 << 26))         // exponent sentinel (int)

__device__ float g_alpha_last[BB];
__device__ unsigned int g_done_ctr = 0;

__device__ __forceinline__ float f_lg2(float x) {
    float r; asm("lg2.approx.f32 %0, %1;" : "=f"(r) : "f"(x)); return r;
}
// 2^k as float, clamped: k>126 -> 2^126, k<-126 -> 0
__device__ __forceinline__ float pow2s(int k) {
    k = (k > 126) ? 126 : k;
    return (k < -126) ? 0.0f : __int_as_float((k + 127) << 23);
}

__device__ __forceinline__ void mbar_init(uint32_t a, uint32_t cnt) {
    asm volatile("mbarrier.init.shared.b64 [%0], %1;" :: "r"(a), "r"(cnt) : "memory");
}
__device__ __forceinline__ void mbar_arrive(uint32_t a) {
    asm volatile("mbarrier.arrive.shared.b64 _, [%0];" :: "r"(a) : "memory");
}
__device__ __forceinline__ void mbar_wait(uint32_t a, uint32_t phase) {
    asm volatile(
        "{\n\t.reg .pred P;\n\t"
        "WL_%=:\n\t"
        "mbarrier.try_wait.parity.acquire.cta.shared::cta.b64 P, [%0], %1, 0x989680;\n\t"
        "@P bra.uni WD_%=;\n\t"
        "bra.uni WL_%=;\n\t"
        "WD_%=:\n\t}"
        :: "r"(a), "r"(phase) : "memory");
}

extern __shared__ float sbuf[];   // NBUF buffers of [LL][SROW], probs + 1e-30

// ---------------------------------------------------------------------------
// Recursion kernel: one block per batch, 512 threads (16 warps).
//   warps 0-7 (recursion): warp w carries labels [32w-32, 32w+32), 2 adjacent
//     slots/thread (lanes 0-15 = halo, 16-31 = owned). Linear-domain block-FP
//     alpha (a*2^E): step = p*(a + left*f), no MUFU. Renorm every 16 steps;
//     halo refresh every 32 via smem + bar.sync 1,256. 2 rec warps per SMSP
//     hide each other's latencies.
//   warps 8-15 (convert): LDG.128 -> +1e-30 -> STS; mbarrier ring depth 2.
// ---------------------------------------------------------------------------
__global__ void __launch_bounds__(512, 1)
k_rec(const float* __restrict__ probs,
      const int* __restrict__ text_lengths,
      const int* __restrict__ mel_lengths,
      float* __restrict__ out)
{
    __shared__ float hA[2][8][32];
    __shared__ int   hE[2][8][32];
    __shared__ __align__(8) unsigned long long mbar_store[2 * NBUF];

    const int b    = blockIdx.x;
    const int tid  = threadIdx.x;
    const int warp = tid >> 5;
    const int lane = tid & 31;

    const int tgt_t = __ldg(mel_lengths  + b) - 1;
    const int tgt_l = __ldg(text_lengths + b) - 1;

    const float* pbase = probs + (size_t)b * LL * TT;

    const uint32_t mb = (uint32_t)__cvta_generic_to_shared(mbar_store);
#define FULL_A(s)  (mb + (uint32_t)(s) * 8u)
#define EMPTY_A(s) (mb + 16u + (uint32_t)(s) * 8u)

    if (tid == 0) {
#pragma unroll
        for (int s = 0; s < NBUF; ++s) {
            mbar_init(FULL_A(s), 8);    // one arrive per convert warp
            mbar_init(EMPTY_A(s), 8);   // one arrive per recursion warp
        }
    }
    __syncthreads();

    if (warp >= 8) {
        // ============== convert / producer (copy + 1e-30 floor) ============
        const int wtid = tid - 256;     // 0..255
        for (int c = 0; c < NCH; ++c) {
            const int s = c & 1, u = c >> 1;
            mbar_wait(EMPTY_A(s), (u & 1) ^ 1);
            float* buf = sbuf + s * BUF_FLOATS;
            const float* gsrc = pbase + c * TC;
#pragma unroll
            for (int k = 0; k < 16; ++k) {
                const int i   = wtid + k * 256;    // 0..4095
                const int row = i >> 4;            // 16 float4 per 64-float row
                const int c4  = (i & 15) * 4;
                const float4 v = *reinterpret_cast<const float4*>(
                                     gsrc + (size_t)row * TT + c4);
                float* sp = buf + row * SROW + c4;
                sp[0] = v.x + 1e-30f; sp[1] = v.y + 1e-30f;
                sp[2] = v.z + 1e-30f; sp[3] = v.w + 1e-30f;
            }
            if (lane == 0) mbar_arrive(FULL_A(s));
        }
    } else {
        // ======================= recursion / consumer ======================
        // labels: l0 = 32*warp - 32 + 2*lane, l1 = l0 + 1
        const int l0 = 32 * warp - 32 + 2 * lane;
        const int cr0 = ((l0 >= 0)     ? l0     : 0) * SROW;
        const int cr1 = ((l0 + 1 >= 0) ? l0 + 1 : 0) * SROW;

        // owned slot of label tgt_l: warp tgt_l>>5, lane 16 + (tgt_l&31)/2
        const int  wt     = tgt_l >> 5;
        const int  lane_t = 16 + ((tgt_l & 31) >> 1);
        const bool mine   = (warp == wt) && (lane == lane_t);
        const int  msel   = tgt_l & 1;
        const int  ct     = tgt_t >> 6;            // chunk containing tgt_t

        float a0 = 0.f, a1 = 0.f;
        int   e0 = E_SENT, e1 = E_SENT;
        float f0 = 0.f, f1 = 0.f;
        int   h  = 0;                              // halo parity

#define SNAPVAL(AV, EV) ((AV) == 0.0f ? -1e30f : (f_lg2(AV) + (float)(EV)) * LN2)

#define STEP(BUFC, J, SNAPJ)                                              \
        {                                                                 \
            float p0 = (BUFC)[cr0 + (J)];                                 \
            float p1 = (BUFC)[cr1 + (J)];                                 \
            float sh = __shfl_up_sync(0xffffffffu, a1, 1);                \
            float t0 = fmaf(sh, f0, a0);     /* lane0: f0==0 */           \
            float t1 = fmaf(a0, f1, a1);                                  \
            a0 = t0 * p0; a1 = t1 * p1;                                   \
            if ((J) == (SNAPJ)) {            /* warp-uniform compare */   \
                if (mine) {                                               \
                    float av = msel ? a1 : a0;                            \
                    int   ev = msel ? e1 : e0;                            \
                    g_alpha_last[b] = SNAPVAL(av, ev);                    \
                }                                                         \
            }                                                             \
        }

        // Renorm: mantissa-normalize, exponent adoption for dead slots
        // (segmented scan, reach 30 slots >= 16-step mass reach), pairwise
        // rebase, new f's; f0 forced 0 on lane 0 (degradation front).
#define RENORM()                                                          \
        {                                                                 \
            int bi, ex;                                                   \
            bi = __float_as_int(a0); ex = (bi >> 23) & 255;               \
            bool R0 = (ex != 0);                                          \
            if (R0) { e0 += ex - 127;                                     \
                      a0 = __int_as_float((bi & 0x807FFFFF) | 0x3F800000);}\
            else    { a0 = 0.f; e0 = E_SENT; }                            \
            bi = __float_as_int(a1); ex = (bi >> 23) & 255;               \
            bool R1 = (ex != 0);                                          \
            if (R1) { e1 += ex - 127;                                     \
                      a1 = __int_as_float((bi & 0x807FFFFF) | 0x3F800000);}\
            else    { a1 = 0.f; e1 = E_SENT; }                            \
            int lv = R1 ? e1 : (R0 ? e0 : E_SENT);                        \
            int lf = (int)(R0 | R1);                                      \
            _Pragma("unroll")                                             \
            for (int d = 1; d < 16; d <<= 1) {                            \
                int ov = __shfl_up_sync(0xffffffffu, lv, d);              \
                int of = __shfl_up_sync(0xffffffffu, lf, d);              \
                if (lane >= d && !lf) { lv = ov; lf = of; }               \
            }                                                             \
            int Lin = __shfl_up_sync(0xffffffffu, lv, 1);                 \
            if (lane == 0) Lin = E_SENT;                                  \
            int pl = __shfl_up_sync(0xffffffffu, e1, 1);                  \
            if (lane == 0) pl = E_SENT;                                   \
            int P0 = R0 ? ((e0 > pl) ? e0 : pl) : Lin;                    \
            int L1 = R0 ? e0 : Lin;                                       \
            int P1 = R1 ? ((e1 > e0) ? e1 : e0) : L1;                     \
            a0 *= pow2s(e0 - P0);                                         \
            a1 *= pow2s(e1 - P1);                                         \
            int PL = __shfl_up_sync(0xffffffffu, P1, 1);                  \
            if (lane == 0) PL = E_SENT;                                   \
            f0 = pow2s(PL - P0);                                          \
            if (lane == 0) f0 = 0.0f;   /* degradation front */           \
            f1 = pow2s(P0 - P1);                                          \
            e0 = P0; e1 = P1;                                             \
        }

        // Halo refresh: warp w adopts warp w-1's owned values.
#define HALO()                                                            \
        {                                                                 \
            if (warp < 7 && lane >= 16) {                                 \
                const int o = 2 * (lane - 16);                            \
                hA[h & 1][warp][o]     = a0; hE[h & 1][warp][o]     = e0; \
                hA[h & 1][warp][o + 1] = a1; hE[h & 1][warp][o + 1] = e1; \
            }                                                             \
            asm volatile("bar.sync 1, 256;" ::: "memory");                \
            if (warp > 0 && lane < 16) {                                  \
                a0 = hA[h & 1][warp - 1][2 * lane];                       \
                e0 = hE[h & 1][warp - 1][2 * lane];                       \
                a1 = hA[h & 1][warp - 1][2 * lane + 1];                   \
                e1 = hE[h & 1][warp - 1][2 * lane + 1];                   \
            }                                                             \
            h ^= 1;                                                       \
        }

        // ---- chunk 0 (t=0 is init, steps j=1..63) ----
        mbar_wait(FULL_A(0), 0);
        {
            const float* bufc = sbuf;
            const int snap_j = (ct == 0) ? (tgt_t & 63) : -1;
            if (warp == 0 && lane == 16) { a0 = bufc[0]; e0 = 0; } // label 0
            if (tgt_t == 0 && mine)
                g_alpha_last[b] = SNAPVAL(msel ? a1 : a0, msel ? e1 : e0);
            RENORM()
#pragma unroll
            for (int j = 1; j < 16; ++j) STEP(bufc, j, snap_j)
            RENORM()
#pragma unroll
            for (int j = 16; j < 32; ++j) STEP(bufc, j, snap_j)
            HALO()
            RENORM()
#pragma unroll
            for (int j = 32; j < 48; ++j) STEP(bufc, j, snap_j)
            RENORM()
#pragma unroll
            for (int j = 48; j < 64; ++j) STEP(bufc, j, snap_j)
        }
        if (lane == 0) mbar_arrive(EMPTY_A(0));
        HALO()

        // ---- chunks 1..24 ----
        for (int c = 1; c < NCH; ++c) {
            const int s = c & 1, u = c >> 1;
            mbar_wait(FULL_A(s), u & 1);
            const float* bufc = sbuf + s * BUF_FLOATS;
            const int snap_j = (c == ct) ? (tgt_t & 63) : -1;
            RENORM()
#pragma unroll
            for (int j = 0; j < 16; ++j) STEP(bufc, j, snap_j)
            RENORM()
#pragma unroll
            for (int j = 16; j < 32; ++j) STEP(bufc, j, snap_j)
            HALO()
            RENORM()
#pragma unroll
            for (int j = 32; j < 48; ++j) STEP(bufc, j, snap_j)
            RENORM()
#pragma unroll
            for (int j = 48; j < 64; ++j) STEP(bufc, j, snap_j)
            if (lane == 0) mbar_arrive(EMPTY_A(s));
            HALO()
        }
    }

    __syncthreads();

    // last block to finish computes loss = -mean(alpha_last)
    if (tid == 0) {
        __threadfence();
        unsigned old = atomicAdd(&g_done_ctr, 1u);
        if (old == BB - 1) {
            g_done_ctr = 0;                          // reset for graph replay
            __threadfence();
            float s = 0.0f;
#pragma unroll
            for (int i = 0; i < BB; ++i) s += g_alpha_last[i];
            out[0] = -s * (1.0f / BB);
        }
    }
}

// ---------------------------------------------------------------------------
// Elementwise kernel (forked stream): out[1+i] = log(probs[i] + 1e-30)
// ---------------------------------------------------------------------------
__global__ void k_elem(const float* __restrict__ probs,
                       float* __restrict__ mat,     // = out + 1
                       long long nvec)              // number of float4
{
    long long i = (long long)blockIdx.x * blockDim.x + threadIdx.x;
    long long stride = (long long)gridDim.x * blockDim.x;
    const float4* p4 = reinterpret_cast<const float4*>(probs);
    for (; i < nvec; i += stride) {
        float4 v = p4[i];
        long long o = i * 4;
        mat[o + 0] = __logf(v.x + 1e-30f);
        mat[o + 1] = __logf(v.y + 1e-30f);
        mat[o + 2] = __logf(v.z + 1e-30f);
        mat[o + 3] = __logf(v.w + 1e-30f);
    }
}

// ---------------------------------------------------------------------------
extern "C" void kernel_launch(void* const* d_in, const int* in_sizes, int n_in,
                              void* d_out, int out_size)
{
    const float* probs        = (const float*)d_in[0];
    // d_in[1] = melspec (unused by the computation)
    const int*   text_lengths = (const int*)d_in[2];
    const int*   mel_lengths  = (const int*)d_in[3];

    float* out = (float*)d_out;   // out[0] = loss, out[1..] = log matrix

    static cudaStream_t s2 = nullptr;
    static cudaEvent_t  evF = nullptr, evJ = nullptr;
    if (s2 == nullptr) {
        cudaStreamCreateWithFlags(&s2, cudaStreamNonBlocking);
        cudaEventCreateWithFlags(&evF, cudaEventDisableTiming);
        cudaEventCreateWithFlags(&evJ, cudaEventDisableTiming);
        cudaFuncSetAttribute(k_rec, cudaFuncAttributeMaxDynamicSharedMemorySize,
                             SMEM_BYTES);
    }

    const long long nvec = (long long)BB * LL * TT / 4;

    // fork: elementwise on s2, recursion on the main (capture) stream
    cudaEventRecord(evF, 0);
    cudaStreamWaitEvent(s2, evF, 0);
    k_elem<<<1184, 256, 0, s2>>>(probs, out + 1, nvec);
    cudaEventRecord(evJ, s2);

    k_rec<<<BB, 512, SMEM_BYTES, 0>>>(probs, text_lengths, mel_lengths, out);

    // join
    cudaStreamWaitEvent(0, evJ, 0);
    (void)in_sizes; (void)n_in; (void)out_size;
}